// round 12
// baseline (speedup 1.0000x reference)
#include <cuda_runtime.h>
#include <cuda_fp16.h>
#include <mma.h>
#include <cstdint>

using namespace nvcuda;

// ----------------------------------------------------------------------------
// out[64,14336](fp32) = (x[64,4096]*xs) @ (w[14336,4096]*ws)^T
// int32 inputs (harness promotes int8->int32), fp32 scales/output.
// R12 = R11 resubmitted (R11 bench died to container infra, not the kernel):
// W and X: LDG.128 -> regs -> cvt -> fp16 STS (no raw int32 smem round trip).
// Split-K x4 (448 CTAs, 3/SM). Scale in-fragment + atomicAdd into pre-zeroed
// out (exact integer fp32 adds -> deterministic). No reduce kernel.
// ----------------------------------------------------------------------------

#define M_TOK   64
#define KDIM    4096
#define NOUT    14336
#define TILE_N  128
#define SPLITS  4
#define KR      (KDIM / SPLITS)            // 1024 per split
#define KC      32                         // K ints per iteration
#define ITERS   (KR / KC)                  // 32
#define WSTRIDE 40                         // halves per fp16 row (32 + 8 pad)
#define XSM_OFF (TILE_N * WSTRIDE * 2)     // 10240
#define SMEM_TOTAL (XSM_OFF + M_TOK * WSTRIDE * 2)   // 15360
#define OUT_ELEMS ((long)M_TOK * NOUT)     // 917504

__global__ void zero_kernel(float* out, long n) {
    long i = (long)blockIdx.x * blockDim.x + threadIdx.x;
    if (i < n) out[i] = 0.0f;
}

// 4 int32 -> 4 fp16 packed (exact for small ints)
__device__ __forceinline__ uint2 cvt4(uint4 v) {
    __half2 lo = __halves2half2(__int2half_rn((int)v.x), __int2half_rn((int)v.y));
    __half2 hi = __halves2half2(__int2half_rn((int)v.z), __int2half_rn((int)v.w));
    uint2 r;
    r.x = *reinterpret_cast<uint32_t*>(&lo);
    r.y = *reinterpret_cast<uint32_t*>(&hi);
    return r;
}

__global__ __launch_bounds__(256, 3) void Model_89704686944640_kernel(
    const int* __restrict__ w, const int* __restrict__ x,
    const float* __restrict__ s0, const float* __restrict__ s1,
    float* __restrict__ out) {
    extern __shared__ char smem[];
    __half* const wsmh = reinterpret_cast<__half*>(smem);            // [128][40]
    __half* const xsmh = reinterpret_cast<__half*>(smem + XSM_OFF);  // [64][40]

    const int tid = threadIdx.x;
    const int wid = tid >> 5;
    const int lane = tid & 31;
    const int fg = wid & 3;                    // feature group (4 x 32)
    const int tg = wid >> 2;                   // token group (2 x 32)
    const int tile = blockIdx.x;
    const int split = blockIdx.y;
    const long wbase = (long)tile * TILE_N * KDIM;
    const int kbase0 = split * KR;

    // load coords: W 1024 16B-chunks -> 4/thr; X 512 -> 2/thr
    const int wrow[4] = { (tid + 0) >> 3, (tid + 256) >> 3,
                          (tid + 512) >> 3, (tid + 768) >> 3 };
    const int xrow[2] = { (tid + 0) >> 3, (tid + 256) >> 3 };
    const int ch4 = (tid & 7) * 4;             // int offset within row

    wmma::fragment<wmma::accumulator, 16, 16, 16, float> c00, c01, c10, c11;
    wmma::fill_fragment(c00, 0.0f); wmma::fill_fragment(c01, 0.0f);
    wmma::fill_fragment(c10, 0.0f); wmma::fill_fragment(c11, 0.0f);

    // prologue: prefetch iter 0
    uint4 wr[4], xr[2];
    {
        const int koff = kbase0;
#pragma unroll
        for (int r = 0; r < 4; r++)
            wr[r] = *reinterpret_cast<const uint4*>(w + wbase + (long)wrow[r] * KDIM + koff + ch4);
#pragma unroll
        for (int r = 0; r < 2; r++)
            xr[r] = *reinterpret_cast<const uint4*>(x + (long)xrow[r] * KDIM + koff + ch4);
    }

    for (int i = 0; i < ITERS; i++) {
        __syncthreads();   // previous iteration's tiles fully consumed

        // convert regs -> fp16 tiles
#pragma unroll
        for (int r = 0; r < 4; r++)
            *reinterpret_cast<uint2*>(&wsmh[wrow[r] * WSTRIDE + ch4]) = cvt4(wr[r]);
#pragma unroll
        for (int r = 0; r < 2; r++)
            *reinterpret_cast<uint2*>(&xsmh[xrow[r] * WSTRIDE + ch4]) = cvt4(xr[r]);
        __syncthreads();   // tiles ready

        // prefetch next iteration (hidden behind compute + co-resident CTAs)
        if (i + 1 < ITERS) {
            const int koff = kbase0 + (i + 1) * KC;
#pragma unroll
            for (int r = 0; r < 4; r++)
                wr[r] = *reinterpret_cast<const uint4*>(w + wbase + (long)wrow[r] * KDIM + koff + ch4);
#pragma unroll
            for (int r = 0; r < 2; r++)
                xr[r] = *reinterpret_cast<const uint4*>(x + (long)xrow[r] * KDIM + koff + ch4);
        }

        // compute: 2 k-steps of 16
#pragma unroll
        for (int ks = 0; ks < 2; ks++) {
            wmma::fragment<wmma::matrix_b, 16, 16, 16, __half, wmma::col_major> b0, b1;
            wmma::load_matrix_sync(b0, wsmh + (fg * 32) * WSTRIDE + ks * 16, WSTRIDE);
            wmma::load_matrix_sync(b1, wsmh + (fg * 32 + 16) * WSTRIDE + ks * 16, WSTRIDE);
            wmma::fragment<wmma::matrix_a, 16, 16, 16, __half, wmma::row_major> a0, a1;
            wmma::load_matrix_sync(a0, xsmh + (tg * 32) * WSTRIDE + ks * 16, WSTRIDE);
            wmma::load_matrix_sync(a1, xsmh + (tg * 32 + 16) * WSTRIDE + ks * 16, WSTRIDE);
            wmma::mma_sync(c00, a0, b0, c00);
            wmma::mma_sync(c01, a0, b1, c01);
            wmma::mma_sync(c10, a1, b0, c10);
            wmma::mma_sync(c11, a1, b1, c11);
        }
    }

    // ---- epilogue: scale, stage per-warp, atomicAdd (exact integer adds) ----
    float sc = (s0 ? s0[0] : 1.0f) * (s1 ? s1[0] : 1.0f);
#pragma unroll
    for (int i = 0; i < c00.num_elements; i++) {
        c00.x[i] *= sc; c01.x[i] *= sc; c10.x[i] *= sc; c11.x[i] *= sc;
    }
    __syncthreads();   // done with fp16 tiles; reuse smem as fp32 scratch
    float* scr = reinterpret_cast<float*>(smem) + wid * 256;   // 1KB per warp
    const long colbase = (long)tile * TILE_N + fg * 32;
    const int er = lane >> 1;            // 0..15
    const int ec = (lane & 1) * 8;       // 0 or 8

    wmma::fragment<wmma::accumulator, 16, 16, 16, float>* frag[4] = {&c00, &c01, &c10, &c11};
#pragma unroll
    for (int f = 0; f < 4; f++) {
        wmma::store_matrix_sync(scr, *frag[f], 16, wmma::mem_row_major);
        __syncwarp();
        const long tok = tg * 32 + (f >> 1) * 16 + er;
        float* dst = out + tok * NOUT + colbase + (f & 1) * 16 + ec;
#pragma unroll
        for (int j = 0; j < 8; j++)
            atomicAdd(dst + j, scr[er * 16 + ec + j]);
        __syncwarp();
    }
}

extern "C" void kernel_launch(void* const* d_in, const int* in_sizes, int n_in,
                              void* d_out, int out_size) {
    const int* w_q = nullptr;
    const int* x_q = nullptr;
    const float* s0 = nullptr;
    const float* s1 = nullptr;
    for (int i = 0; i < n_in; i++) {
        long n = in_sizes[i];
        if (n == (long)NOUT * KDIM) w_q = (const int*)d_in[i];
        else if (n == (long)M_TOK * KDIM) x_q = (const int*)d_in[i];
        else if (n <= 1) { if (!s0) s0 = (const float*)d_in[i]; else if (!s1) s1 = (const float*)d_in[i]; }
    }
    if (!x_q && n_in > 0) x_q = (const int*)d_in[0];
    if (!s0 && n_in > 1) s0 = (const float*)d_in[1];
    if (!w_q && n_in > 2) w_q = (const int*)d_in[2];
    if (!s1 && n_in > 3) s1 = (const float*)d_in[3];
    float* out = (float*)d_out;

    // zero the whole output (atomic accumulation target; graph-replay safe)
    long n = (long)out_size;
    zero_kernel<<<(int)((n + 255) / 256), 256>>>(out, n);

    cudaFuncSetAttribute(Model_89704686944640_kernel,
                         cudaFuncAttributeMaxDynamicSharedMemorySize, SMEM_TOTAL);
    dim3 grid(NOUT / TILE_N, SPLITS);
    Model_89704686944640_kernel<<<grid, 256, SMEM_TOTAL>>>(w_q, x_q, s0, s1, out);
}

// round 13
// speedup vs baseline: 1.0945x; 1.0945x over previous
#include <cuda_runtime.h>
#include <cuda_fp16.h>
#include <mma.h>
#include <cstdint>

using namespace nvcuda;

// ----------------------------------------------------------------------------
// out[64,14336](fp32) = (x[64,4096]*xs) @ (w[14336,4096]*ws)^T
// int32 inputs (harness promotes int8->int32), fp32 scales/output.
// R13 hybrid: W = 3-stage cp.async raw int32 pipeline (decoupled from warps,
// R10-proven) + convert pass -> fp16 tile. X = register prefetch (L2-resident,
// short latency; kills X's raw smem round trip). Split-K x4 (448 CTAs, 3/SM).
// Epilogue: scale in-fragment + atomicAdd into pre-zeroed out (exact).
// ----------------------------------------------------------------------------

#define M_TOK   64
#define KDIM    4096
#define NOUT    14336
#define TILE_N  128
#define SPLITS  4
#define KR      (KDIM / SPLITS)            // 1024 per split
#define KC      32                         // K ints per iteration
#define ITERS   (KR / KC)                  // 32
#define STAGES  3
#define RAW_ROW 144                        // bytes per raw W row (128 + 16 pad)
#define W_RAW   (TILE_N * RAW_ROW)         // 18432 per stage
#define WSTRIDE 40                         // halves per fp16 row (32 + 8 pad)
#define WSM_OFF (STAGES * W_RAW)                       // 55296
#define XSM_OFF (WSM_OFF + TILE_N * WSTRIDE * 2)       // 65536
#define SMEM_TOTAL (XSM_OFF + M_TOK * WSTRIDE * 2)     // 70656 (x3 = 212KB/SM)
#define OUT_ELEMS ((long)M_TOK * NOUT)     // 917504

__global__ void zero_kernel(float* out, long n) {
    long i = (long)blockIdx.x * blockDim.x + threadIdx.x;
    if (i < n) out[i] = 0.0f;
}

__device__ __forceinline__ uint32_t smem_u32(const void* p) {
    uint32_t a;
    asm("{ .reg .u64 t; cvta.to.shared.u64 t, %1; cvt.u32.u64 %0, t; }" : "=r"(a) : "l"(p));
    return a;
}

__device__ __forceinline__ void cp_async16(uint32_t smem_dst, const void* gmem_src) {
    asm volatile("cp.async.cg.shared.global [%0], [%1], 16;"
                 :: "r"(smem_dst), "l"(gmem_src) : "memory");
}

// 4 int32 -> 4 fp16 packed (exact for small ints)
__device__ __forceinline__ uint2 cvt4(uint4 v) {
    __half2 lo = __halves2half2(__int2half_rn((int)v.x), __int2half_rn((int)v.y));
    __half2 hi = __halves2half2(__int2half_rn((int)v.z), __int2half_rn((int)v.w));
    uint2 r;
    r.x = *reinterpret_cast<uint32_t*>(&lo);
    r.y = *reinterpret_cast<uint32_t*>(&hi);
    return r;
}

__global__ __launch_bounds__(256, 3) void Model_89704686944640_kernel(
    const int* __restrict__ w, const int* __restrict__ x,
    const float* __restrict__ s0, const float* __restrict__ s1,
    float* __restrict__ out) {
    extern __shared__ char smem[];
    __half* const wsmh = reinterpret_cast<__half*>(smem + WSM_OFF);  // [128][40]
    __half* const xsmh = reinterpret_cast<__half*>(smem + XSM_OFF);  // [64][40]
    const uint32_t raw_base = smem_u32(smem);

    const int tid = threadIdx.x;
    const int wid = tid >> 5;
    const int lane = tid & 31;
    const int fg = wid & 3;                    // feature group (4 x 32)
    const int tg = wid >> 2;                   // token group (2 x 32)
    const int tile = blockIdx.x;
    const int split = blockIdx.y;
    const long wbase = (long)tile * TILE_N * KDIM;
    const int kbase0 = split * KR;

    // W: 1024 16B-chunks/iter -> 4/thr ; X: 512 -> 2/thr
    // chunk idx -> row = idx>>3, ch = idx&7
    const int ch = tid & 7;
    const int ch4 = ch * 4;
    const int wrow[4] = { (tid + 0) >> 3, (tid + 256) >> 3,
                          (tid + 512) >> 3, (tid + 768) >> 3 };
    const int xrow[2] = { (tid + 0) >> 3, (tid + 256) >> 3 };

    wmma::fragment<wmma::accumulator, 16, 16, 16, float> c00, c01, c10, c11;
    wmma::fill_fragment(c00, 0.0f); wmma::fill_fragment(c01, 0.0f);
    wmma::fill_fragment(c10, 0.0f); wmma::fill_fragment(c11, 0.0f);

    // ---- prologue ----
    uint4 xr[2];
#pragma unroll
    for (int r = 0; r < 2; r++)                // X iter 0 into registers
        xr[r] = *reinterpret_cast<const uint4*>(x + (long)xrow[r] * KDIM + kbase0 + ch4);
#pragma unroll
    for (int st = 0; st < STAGES; st++) {      // W stages 0..2 via cp.async
        const int koff = kbase0 + st * KC;
        const uint32_t sraw = raw_base + st * W_RAW;
#pragma unroll
        for (int r = 0; r < 4; r++)
            cp_async16(sraw + wrow[r] * RAW_ROW + ch * 16,
                       w + wbase + (long)wrow[r] * KDIM + koff + ch4);
        asm volatile("cp.async.commit_group;" ::: "memory");
    }

    // ---- main loop ----
    for (int i = 0; i < ITERS; i++) {
        asm volatile("cp.async.wait_group %0;" :: "n"(STAGES - 1) : "memory");
        __syncthreads();   // W stage i arrived; previous tiles consumed

        const int s = i % STAGES;
        char* rawS = smem + s * W_RAW;

        // convert W raw -> fp16 tile
#pragma unroll
        for (int r = 0; r < 4; r++) {
            uint4 v = *reinterpret_cast<const uint4*>(rawS + wrow[r] * RAW_ROW + ch * 16);
            *reinterpret_cast<uint2*>(&wsmh[wrow[r] * WSTRIDE + ch4]) = cvt4(v);
        }
        // convert X regs -> fp16 tile
#pragma unroll
        for (int r = 0; r < 2; r++)
            *reinterpret_cast<uint2*>(&xsmh[xrow[r] * WSTRIDE + ch4]) = cvt4(xr[r]);
        __syncthreads();   // tiles ready; raw stage s free

        // refill: X regs for iter i+1 (L2-latency, hidden); W stage i+3
        if (i + 1 < ITERS) {
            const int koff = kbase0 + (i + 1) * KC;
#pragma unroll
            for (int r = 0; r < 2; r++)
                xr[r] = *reinterpret_cast<const uint4*>(x + (long)xrow[r] * KDIM + koff + ch4);
        }
        if (i + STAGES < ITERS) {
            const int koff = kbase0 + (i + STAGES) * KC;
            const uint32_t sraw = raw_base + s * W_RAW;
#pragma unroll
            for (int r = 0; r < 4; r++)
                cp_async16(sraw + wrow[r] * RAW_ROW + ch * 16,
                           w + wbase + (long)wrow[r] * KDIM + koff + ch4);
        }
        asm volatile("cp.async.commit_group;" ::: "memory");

        // compute: 2 k-steps of 16
#pragma unroll
        for (int ks = 0; ks < 2; ks++) {
            wmma::fragment<wmma::matrix_b, 16, 16, 16, __half, wmma::col_major> b0, b1;
            wmma::load_matrix_sync(b0, wsmh + (fg * 32) * WSTRIDE + ks * 16, WSTRIDE);
            wmma::load_matrix_sync(b1, wsmh + (fg * 32 + 16) * WSTRIDE + ks * 16, WSTRIDE);
            wmma::fragment<wmma::matrix_a, 16, 16, 16, __half, wmma::row_major> a0, a1;
            wmma::load_matrix_sync(a0, xsmh + (tg * 32) * WSTRIDE + ks * 16, WSTRIDE);
            wmma::load_matrix_sync(a1, xsmh + (tg * 32 + 16) * WSTRIDE + ks * 16, WSTRIDE);
            wmma::mma_sync(c00, a0, b0, c00);
            wmma::mma_sync(c01, a0, b1, c01);
            wmma::mma_sync(c10, a1, b0, c10);
            wmma::mma_sync(c11, a1, b1, c11);
        }
    }

    // ---- epilogue: scale, stage per-warp, atomicAdd (exact integer adds) ----
    float sc = (s0 ? s0[0] : 1.0f) * (s1 ? s1[0] : 1.0f);
#pragma unroll
    for (int i = 0; i < c00.num_elements; i++) {
        c00.x[i] *= sc; c01.x[i] *= sc; c10.x[i] *= sc; c11.x[i] *= sc;
    }
    __syncthreads();   // done with tiles; reuse smem as fp32 scratch
    float* scr = reinterpret_cast<float*>(smem) + wid * 256;   // 1KB per warp
    const long colbase = (long)tile * TILE_N + fg * 32;
    const int er = lane >> 1;            // 0..15
    const int ec = (lane & 1) * 8;       // 0 or 8

    wmma::fragment<wmma::accumulator, 16, 16, 16, float>* frag[4] = {&c00, &c01, &c10, &c11};
#pragma unroll
    for (int f = 0; f < 4; f++) {
        wmma::store_matrix_sync(scr, *frag[f], 16, wmma::mem_row_major);
        __syncwarp();
        const long tok = tg * 32 + (f >> 1) * 16 + er;
        float* dst = out + tok * NOUT + colbase + (f & 1) * 16 + ec;
#pragma unroll
        for (int j = 0; j < 8; j++)
            atomicAdd(dst + j, scr[er * 16 + ec + j]);
        __syncwarp();
    }
}

extern "C" void kernel_launch(void* const* d_in, const int* in_sizes, int n_in,
                              void* d_out, int out_size) {
    const int* w_q = nullptr;
    const int* x_q = nullptr;
    const float* s0 = nullptr;
    const float* s1 = nullptr;
    for (int i = 0; i < n_in; i++) {
        long n = in_sizes[i];
        if (n == (long)NOUT * KDIM) w_q = (const int*)d_in[i];
        else if (n == (long)M_TOK * KDIM) x_q = (const int*)d_in[i];
        else if (n <= 1) { if (!s0) s0 = (const float*)d_in[i]; else if (!s1) s1 = (const float*)d_in[i]; }
    }
    if (!x_q && n_in > 0) x_q = (const int*)d_in[0];
    if (!s0 && n_in > 1) s0 = (const float*)d_in[1];
    if (!w_q && n_in > 2) w_q = (const int*)d_in[2];
    if (!s1 && n_in > 3) s1 = (const float*)d_in[3];
    float* out = (float*)d_out;

    // zero the whole output (atomic accumulation target; graph-replay safe)
    long n = (long)out_size;
    zero_kernel<<<(int)((n + 255) / 256), 256>>>(out, n);

    cudaFuncSetAttribute(Model_89704686944640_kernel,
                         cudaFuncAttributeMaxDynamicSharedMemorySize, SMEM_TOTAL);
    dim3 grid(NOUT / TILE_N, SPLITS);
    Model_89704686944640_kernel<<<grid, 256, SMEM_TOTAL>>>(w_q, x_q, s0, s1, out);
}